// round 1
// baseline (speedup 1.0000x reference)
#include <cuda_runtime.h>
#include <cstdint>

// MaxUnpooling2D: updates [16,64,64,256] f32, mask [16,64,64,256] i32
// (flattened per-batch output index), out [16,128,128,256] f32.
//
// Key property: each pooled element scatters into its OWN 2x2 window at the
// SAME channel => output cells are covered exactly once by the union of all
// (thread, window-cell) stores. So we fuse zero-fill + scatter: each thread
// owns 4 channels of one pooled element and writes all 4 window cells as
// float4 (selected value or zero). Fully dense, fully coalesced.

#define B_  16
#define H_  64
#define W_  64
#define C_  256
#define WO_ 128
#define HOWOC_ (128 * 128 * 256)   // per-batch output elements

__global__ void __launch_bounds__(256) max_unpool_kernel(
    const float4* __restrict__ upd,
    const int4*   __restrict__ msk,
    float*        __restrict__ out,
    int n4)
{
    int t = blockIdx.x * blockDim.x + threadIdx.x;
    if (t >= n4) return;

    int4   m = msk[t];
    float4 u = upd[t];

    // Decode coords from linear float4 index. C/4 = 64, W = 64, H = 64.
    int c4 = t & 63;
    int w  = (t >> 6) & 63;
    int h  = (t >> 12) & 63;
    int b  = t >> 18;

    // Per-batch flattened base address of window cell (di=0, dj=0), channel 4*c4.
    int base = h * (2 * WO_ * C_) + w * (2 * C_) + (c4 << 2);

    float* ob = out + (size_t)b * HOWOC_ + base;

    // Window-cell offsets: (di*Wo + dj)*C for (di,dj) in {0,1}^2.
    const int off1 = C_;             // (0,1)
    const int off2 = WO_ * C_;       // (1,0)
    const int off3 = WO_ * C_ + C_;  // (1,1)
    const int offs[4] = {0, off1, off2, off3};

#pragma unroll
    for (int k = 0; k < 4; k++) {
        int a = base + offs[k];
        float4 v;
        v.x = (m.x == a + 0) ? u.x : 0.0f;
        v.y = (m.y == a + 1) ? u.y : 0.0f;
        v.z = (m.z == a + 2) ? u.z : 0.0f;
        v.w = (m.w == a + 3) ? u.w : 0.0f;
        *reinterpret_cast<float4*>(ob + offs[k]) = v;
    }
}

extern "C" void kernel_launch(void* const* d_in, const int* in_sizes, int n_in,
                              void* d_out, int out_size)
{
    const float4* upd = (const float4*)d_in[0];
    const int4*   msk = (const int4*)d_in[1];
    float*        out = (float*)d_out;

    int n  = in_sizes[0];       // 16*64*64*256 = 16,777,216
    int n4 = n >> 2;            // 4,194,304 float4 work items

    int threads = 256;
    int blocks  = (n4 + threads - 1) / threads;   // 16384
    max_unpool_kernel<<<blocks, threads>>>(upd, msk, out, n4);
}